// round 7
// baseline (speedup 1.0000x reference)
#include <cuda_runtime.h>
#include <cuda_bf16.h>

// Problem constants
#define B_  8
#define C_  256
#define O_  256
#define H_  64
#define W_  64
#define HW_ 4096
#define KK_ 9
#define P_  32   // positions per CTA

// ONLY small static scratch (container has a tight device-memory margin):
// weight retiled to [kk][c][o] = 2.25 MiB.
__device__ float g_wT[KK_ * C_ * O_];

// ---------------------------------------------------------------------------
// packed fp32x2 helpers (sm_103a: fma.rn.f32x2 = 2 FMAs/lane per issue slot)
// ---------------------------------------------------------------------------
__device__ __forceinline__ unsigned long long pk2(float v) {
    unsigned long long r;
    asm("mov.b64 %0, {%1, %1};" : "=l"(r) : "f"(v));
    return r;
}
__device__ __forceinline__ void fma2(unsigned long long& d,
                                     unsigned long long a,
                                     unsigned long long b) {
    asm("fma.rn.f32x2 %0, %1, %2, %0;" : "+l"(d) : "l"(a), "l"(b));
}
__device__ __forceinline__ float2 upk2(unsigned long long v) {
    float2 r;
    asm("mov.b64 {%0, %1}, %2;" : "=f"(r.x), "=f"(r.y) : "l"(v));
    return r;
}

// ---------------------------------------------------------------------------
// Kernel 1: weight (O,C,3,3) -> wT[kk][c][o]
// ---------------------------------------------------------------------------
__global__ void dcn_transpose_w(const float* __restrict__ w) {
    int i = blockIdx.x * 256 + threadIdx.x;
    if (i >= KK_ * C_ * O_) return;
    int kk  = i >> 16;
    int rem = i & 65535;
    int c = rem >> 8;
    int o = rem & 255;
    g_wT[i] = w[o * 2304 + c * 9 + kk];
}

// ---------------------------------------------------------------------------
// Kernel 2: fused bilinear-im2col + GEMM.
// CTA: 32 consecutive hw positions (one row segment) x all 256 out channels.
// Gather reads NCHW directly with warp-lane = position (addresses nearly
// consecutive within a c-plane). Per (kk, c-chunk of 32): stage w tile
// (32 KB smem) + gather s tile (32c x 32p), then 8o x 4p register-tiled
// GEMM with packed f32x2 FMAs (pack over the o-dimension).
// ---------------------------------------------------------------------------
__global__ __launch_bounds__(256, 2)
void dcn_main(const float* __restrict__ x,      // (B, C, H, W)
              const float* __restrict__ coff,   // (B, 2*KK, H, W)
              const float* __restrict__ cwt,    // (B, KK, H, W)
              const float* __restrict__ bias,   // (O)
              float* __restrict__ out)          // (B, O, H, W)
{
    __shared__ float w_sm[32 * 256];   // [c_local][o]   32 KB
    __shared__ float s_sm[32 * 33];    // [c_local][p]   pad-33, conflict-free
    __shared__ int   pspat_sm[P_ * 5]; // 4 corner spatial indices, stride-5 pad
    __shared__ float pwgt_sm[P_ * 5];  // folded bilinear*coord_weight (0 if OOB)

    const int cta = blockIdx.x;
    const int b   = cta >> 7;            // 128 CTAs per batch
    const int p0  = (cta & 127) << 5;    // hw base (multiple of 32 => one row)
    const int y   = p0 >> 6;
    const int xb  = p0 & 63;

    const int tid = threadIdx.x;
    const int wrp = tid >> 5;            // warp id 0..7
    const int p   = tid & 31;            // gather: lane = position
    const int to  = tid >> 3;            // GEMM: o_base = to*8
    const int tp  = tid & 7;             // GEMM: p_base = tp*4

    const float* xb_base = x + ((long)b << 20);   // b*C*HW

    unsigned long long acc[4][4];        // [o-pair][p], packed (o_even, o_odd)
#pragma unroll
    for (int i = 0; i < 4; ++i)
#pragma unroll
        for (int j = 0; j < 4; ++j) acc[i][j] = 0ull;

    for (int kk = 0; kk < KK_; ++kk) {
        // ---- per-tap per-position bilinear prep (warp 0) ----
        if (tid < P_) {
            int xx = xb + tid;
            int base_oy = ((b * 18 + 2 * kk) * 64 + y) * 64 + xx;
            float oy = __ldg(&coff[base_oy]);
            float ox = __ldg(&coff[base_oy + HW_]);
            float cw = __ldg(&cwt[((b * 9 + kk) * 64 + y) * 64 + xx]);
            int ky = kk / 3;
            int kx = kk - ky * 3;
            float py = (float)(y  - 1 + ky) + oy;
            float px = (float)(xx - 1 + kx) + ox;
            float fy = floorf(py), fx = floorf(px);
            int   y0 = (int)fy,    x0 = (int)fx;
            float wy1 = py - fy, wy0 = 1.0f - wy1;
            float wx1 = px - fx, wx0 = 1.0f - wx1;
            bool vy0 = (y0 >= 0)  && (y0 < H_);
            bool vy1 = (y0 >= -1) && (y0 < H_ - 1);
            bool vx0 = (x0 >= 0)  && (x0 < W_);
            bool vx1 = (x0 >= -1) && (x0 < W_ - 1);
            int yc0 = max(0, min(H_ - 1, y0));
            int yc1 = max(0, min(H_ - 1, y0 + 1));
            int xc0 = max(0, min(W_ - 1, x0));
            int xc1 = max(0, min(W_ - 1, x0 + 1));
            pspat_sm[tid * 5 + 0] = (yc0 << 6) + xc0;
            pspat_sm[tid * 5 + 1] = (yc0 << 6) + xc1;
            pspat_sm[tid * 5 + 2] = (yc1 << 6) + xc0;
            pspat_sm[tid * 5 + 3] = (yc1 << 6) + xc1;
            pwgt_sm[tid * 5 + 0] = (vy0 && vx0) ? cw * wy0 * wx0 : 0.0f;
            pwgt_sm[tid * 5 + 1] = (vy0 && vx1) ? cw * wy0 * wx1 : 0.0f;
            pwgt_sm[tid * 5 + 2] = (vy1 && vx0) ? cw * wy1 * wx0 : 0.0f;
            pwgt_sm[tid * 5 + 3] = (vy1 && vx1) ? cw * wy1 * wx1 : 0.0f;
        }
        __syncthreads();

        // every lane caches its position's corner state in registers
        int   sp0 = pspat_sm[p * 5 + 0], sp1 = pspat_sm[p * 5 + 1];
        int   sp2 = pspat_sm[p * 5 + 2], sp3 = pspat_sm[p * 5 + 3];
        float g0  = pwgt_sm[p * 5 + 0],  g1  = pwgt_sm[p * 5 + 1];
        float g2  = pwgt_sm[p * 5 + 2],  g3  = pwgt_sm[p * 5 + 3];

        for (int cc = 0; cc < 8; ++cc) {
            __syncthreads();   // previous GEMM done with s_sm/w_sm

            // ---- stage weight chunk: wT[kk][cc*32..+32][0..255] (contiguous) ----
            {
                const float4* wsrc =
                    (const float4*)(g_wT + (kk << 16) + (cc << 13));
                float4* wdst = (float4*)w_sm;
#pragma unroll
                for (int i = 0; i < 8; ++i)
                    wdst[tid + (i << 8)] = wsrc[tid + (i << 8)];
            }

            // ---- gather s tile: warp w handles c_local = w*4..+3, lane = p ----
            {
                int c_lo = (wrp << 2);                    // c_local base
                const float* plane =
                    xb_base + (((long)((cc << 5) + c_lo)) << 12);
#pragma unroll
                for (int i = 0; i < 4; ++i) {
                    const float* pl = plane + ((long)i << 12);
                    float v = g0 * __ldg(pl + sp0) + g1 * __ldg(pl + sp1)
                            + g2 * __ldg(pl + sp2) + g3 * __ldg(pl + sp3);
                    s_sm[(c_lo + i) * 33 + p] = v;
                }
            }
            __syncthreads();

            // ---- GEMM: acc[o=to*8..+7][p=tp*4..+3] += w[c][o] * s[c][p] ----
            const ulonglong2* wq = (const ulonglong2*)w_sm;  // [c][64 x ull2]
#pragma unroll 4
            for (int c = 0; c < 32; ++c) {
                ulonglong2 wA = wq[(c << 6) + (to << 1)];      // o 0-3
                ulonglong2 wB = wq[(c << 6) + (to << 1) + 1];  // o 4-7
                const float* srow = s_sm + c * 33 + (tp << 2);
                unsigned long long s0 = pk2(srow[0]);
                unsigned long long s1 = pk2(srow[1]);
                unsigned long long s2 = pk2(srow[2]);
                unsigned long long s3 = pk2(srow[3]);
                fma2(acc[0][0], wA.x, s0); fma2(acc[0][1], wA.x, s1);
                fma2(acc[0][2], wA.x, s2); fma2(acc[0][3], wA.x, s3);
                fma2(acc[1][0], wA.y, s0); fma2(acc[1][1], wA.y, s1);
                fma2(acc[1][2], wA.y, s2); fma2(acc[1][3], wA.y, s3);
                fma2(acc[2][0], wB.x, s0); fma2(acc[2][1], wB.x, s1);
                fma2(acc[2][2], wB.x, s2); fma2(acc[2][3], wB.x, s3);
                fma2(acc[3][0], wB.y, s0); fma2(acc[3][1], wB.y, s1);
                fma2(acc[3][2], wB.y, s2); fma2(acc[3][3], wB.y, s3);
            }
        }
        __syncthreads();   // GEMM done before next tap's prep rewrites pspat/pwgt
    }

    // ---- epilogue: unpack, add bias, coalesced float4 stores ----
    const int o0 = to << 3;
#pragma unroll
    for (int oo = 0; oo < 4; ++oo) {
        float2 a0 = upk2(acc[oo][0]);
        float2 a1 = upk2(acc[oo][1]);
        float2 a2 = upk2(acc[oo][2]);
        float2 a3 = upk2(acc[oo][3]);
        int oA = o0 + (oo << 1);
        int oB = oA + 1;
        float bA = bias[oA];
        float bB = bias[oB];
        float4 vA = make_float4(a0.x + bA, a1.x + bA, a2.x + bA, a3.x + bA);
        float4 vB = make_float4(a0.y + bB, a1.y + bB, a2.y + bB, a3.y + bB);
        *(float4*)(out + ((((b << 8) + oA) << 12) + p0 + (tp << 2))) = vA;
        *(float4*)(out + ((((b << 8) + oB) << 12) + p0 + (tp << 2))) = vB;
    }
}

// ---------------------------------------------------------------------------
// Launch: inputs per metadata order: input, coord_offset, coord_weight, weight, bias
// ---------------------------------------------------------------------------
extern "C" void kernel_launch(void* const* d_in, const int* in_sizes, int n_in,
                              void* d_out, int out_size) {
    const float* x    = (const float*)d_in[0];
    const float* coff = (const float*)d_in[1];
    const float* cwt  = (const float*)d_in[2];
    const float* wt   = (const float*)d_in[3];
    const float* bias = (const float*)d_in[4];
    float* out = (float*)d_out;

    dcn_transpose_w<<<(KK_ * C_ * O_ + 255) / 256, 256>>>(wt);
    dcn_main<<<B_ * HW_ / P_, 256>>>(x, coff, cwt, bias, out);
}